// round 5
// baseline (speedup 1.0000x reference)
#include <cuda_runtime.h>
#include <math.h>

// Problem constants
#define BB    64
#define TT    512
#define INSZ  512
#define HH    1024
#define OUTSZ 512
#define NG    4096          // 4*HH gate columns
#define BSEL  63            // only batch row 63 affects the output
#define K0    (INSZ + HH)   // 1536
#define K1    (2 * HH)      // 2048

#define NBLK  128           // persistent blocks (<=148 SMs, wave-1 co-resident)
#define NTHR  256

// ---------------------------------------------------------------------------
// Static device scratch.
// g_W0p/g_W1p: block-packed weight copies, Wp[blk][k][32cols] (128B rows).
//   Written and read ONLY by the owning block -> no coherence traffic.
// h vectors are cross-block shared -> __ldcg/__stcg (L2).
// ---------------------------------------------------------------------------
__device__ float g_W0p[NBLK * K0 * 32];   // 25.2 MB
__device__ float g_W1p[NBLK * K1 * 32];   // 33.6 MB
__device__ float g_h0[2][HH];
__device__ float g_h1[2][HH];
__device__ float g_hist[TT][HH];          // h1(t) history for the final dense

__device__ unsigned g_cnt = 0;
__device__ unsigned g_gen = 0;

__device__ __forceinline__ void gridbar() {
    __syncthreads();
    if (threadIdx.x == 0) {
        volatile unsigned* vgen = &g_gen;
        unsigned gen = *vgen;            // read generation BEFORE arriving
        __threadfence();                 // release my writes to L2
        if (atomicAdd(&g_cnt, 1u) == NBLK - 1) {
            atomicExch(&g_cnt, 0u);
            __threadfence();
            atomicAdd(&g_gen, 1u);       // release everyone
        } else {
            while (*vgen == gen) { }     // volatile spin (L2)
            __threadfence();
        }
    }
    __syncthreads();
}

__device__ __forceinline__ float sigf(float x) {
    return 1.0f / (1.0f + expf(-x));
}

// ---------------------------------------------------------------------------
// Repack this block's 32 gate-columns of W (K x 4096) into Wp (K x 32),
// 128B per k-row. lane -> col: (lane>>3)*HH + hbase + (lane&7).
// ---------------------------------------------------------------------------
__device__ __forceinline__ void repack(const float* __restrict__ W,
                                       float* __restrict__ Wp, int K)
{
    const int tid  = threadIdx.x;
    const int lane = tid & 31;
    const int wrp  = tid >> 5;
    const int hbase = blockIdx.x << 3;
    const int col = (lane >> 3) * HH + hbase + (lane & 7);
    for (int r = wrp; r < K; r += 8)
        Wp[(r << 5) + lane] = __ldg(W + (size_t)r * NG + col);
}

// ---------------------------------------------------------------------------
// One LSTM cell GEMV on packed weights. Thread (s = tid>>3, cg = tid&7):
// s picks one of 32 K-slices, cg picks float4 column-group (gate = cg>>1).
// Each warp-LDG.128 covers 4 full 128B lines (minimum wavefronts).
// ---------------------------------------------------------------------------
template<int K>
__device__ __forceinline__ void gemv_cell(
    const float* __restrict__ Wp,     // packed (K, 32) for this block
    const float* __restrict__ bias_s, // smem: 32 gate biases
    const float* __restrict__ in_sh,  // staged input vector (K floats)
    float* __restrict__ red,          // smem scratch: 32*32 floats
    float* __restrict__ zf,           // smem scratch: 32 floats
    float* __restrict__ c_s,          // smem: 8 cell states (persistent)
    float* __restrict__ h_out,        // global: 8 floats at hbase
    float* __restrict__ hist_out)     // optional second h sink (or null)
{
    const int tid = threadIdx.x;
    const int cg  = tid & 7;
    const int s   = tid >> 3;
    constexpr int KS = K / 32;

    float4 acc = make_float4(0.f, 0.f, 0.f, 0.f);
    const float* wp = Wp + ((s * KS) << 5) + (cg << 2);
    const float* ip = in_sh + s * KS;
#pragma unroll 8
    for (int k = 0; k < KS; k++) {
        float f = ip[k];
        float4 w4 = __ldg((const float4*)wp);
        wp += 32;
        acc.x = fmaf(f, w4.x, acc.x);
        acc.y = fmaf(f, w4.y, acc.y);
        acc.z = fmaf(f, w4.z, acc.z);
        acc.w = fmaf(f, w4.w, acc.w);
    }
    ((float4*)red)[(s << 3) + cg] = acc;   // red[s*32 + cg*4 + e]
    __syncthreads();

    if (tid < 32) {                        // tid = cidx = gate*8 + j
        float sum = 0.f;
#pragma unroll
        for (int ss = 0; ss < 32; ss++) sum += red[(ss << 5) + tid];
        zf[tid] = sum + bias_s[tid];
    }
    __syncthreads();

    if (tid < 8) {
        int j = tid;
        float zi = zf[j], zj = zf[8 + j], zff = zf[16 + j], zo = zf[24 + j];
        float cn = sigf(zff + 1.0f) * c_s[j] + sigf(zi) * tanhf(zj);
        c_s[j] = cn;
        float h = sigf(zo) * tanhf(cn);
        __stcg(h_out + j, h);
        if (hist_out) __stcg(hist_out + j, h);
    }
    __syncthreads();   // protect red/zf reuse next phase
}

// ---------------------------------------------------------------------------
// Single persistent kernel: repack, init, 512 x (layer0 | bar | layer1 | bar),
// then the final dense over the h1 history: out[t][o], t = 0..511.
// ---------------------------------------------------------------------------
__global__ __launch_bounds__(NTHR) void lstm_persistent(
    const float* __restrict__ X,
    const float* __restrict__ state,
    const float* __restrict__ W0, const float* __restrict__ b0,
    const float* __restrict__ W1, const float* __restrict__ b1,
    const float* __restrict__ Wd, const float* __restrict__ bd,
    float* __restrict__ out)
{
    __shared__ __align__(16) float sp[4160];   // in_sh(2048) | red(1024) | zf(32)
    __shared__ float c0_s[8], c1_s[8];
    __shared__ float b0_s[32], b1_s[32];
    float* in_sh = sp;
    float* red   = sp + 2048;
    float* zf    = sp + 3072;

    const int tid   = threadIdx.x;
    const int hbase = blockIdx.x << 3;

    // ---- one-time: repack this block's weight columns (block-private) ----
    float* W0p = g_W0p + (size_t)blockIdx.x * K0 * 32;
    float* W1p = g_W1p + (size_t)blockIdx.x * K1 * 32;
    repack(W0, W0p, K0);
    repack(W1, W1p, K1);

    // ---- init from state row 63: [c0 | h0 | c1 | h1] ----
    const float* srow = state + (size_t)BSEL * 4 * HH;
    if (blockIdx.x == 0) {
        for (int i = tid; i < HH; i += NTHR) {
            __stcg(&g_h0[0][i], srow[HH + i]);
            __stcg(&g_h1[0][i], srow[3 * HH + i]);
        }
    }
    if (tid < 8) {
        c0_s[tid] = srow[hbase + tid];
        c1_s[tid] = srow[2 * HH + hbase + tid];
    }
    if (tid < 32) {
        int col = (tid >> 3) * HH + hbase + (tid & 7);
        b0_s[tid] = b0[col];
        b1_s[tid] = b1[col];
    }
    gridbar();   // h0/h1 init visible everywhere (repack needs no barrier)

    // ---- time loop (batch row 63 only) ----
    const float* Xrow = X + (size_t)BSEL * TT * INSZ;
    int p = 0;
    for (int t = 0; t < TT; t++) {
        // phase A: layer 0, input = [x_t (512), h0_prev (1024)], K = 1536
        const float* xt = Xrow + t * INSZ;
        if (tid < 128)
            ((float4*)in_sh)[tid] = __ldg((const float4*)xt + tid);
        ((float4*)(in_sh + 512))[tid] = __ldcg((const float4*)&g_h0[p][0] + tid);
        __syncthreads();
        gemv_cell<K0>(W0p, b0_s, in_sh, red, zf, c0_s,
                      &g_h0[p ^ 1][hbase], (float*)0);
        gridbar();

        // phase B: layer 1, input = [h0_cur (1024), h1_prev (1024)], K = 2048
        ((float4*)in_sh)[tid]          = __ldcg((const float4*)&g_h0[p ^ 1][0] + tid);
        ((float4*)(in_sh + 1024))[tid] = __ldcg((const float4*)&g_h1[p][0] + tid);
        __syncthreads();
        gemv_cell<K1>(W1p, b1_s, in_sh, red, zf, c1_s,
                      &g_h1[p ^ 1][hbase], &g_hist[t][hbase]);
        gridbar();
        p ^= 1;
    }

    // ---- dense: out[t][o] = hist[t] @ Wd + bd, block owns 4 t-rows ----
    {
        int t0 = blockIdx.x << 2;
#pragma unroll
        for (int r = 0; r < 4; r++)
            ((float4*)sp)[(r << 8) + tid] =
                __ldcg((const float4*)&g_hist[t0 + r][0] + tid);
        __syncthreads();

        int o2 = tid << 1;
        float bv0 = bd[o2], bv1 = bd[o2 + 1];
        float acc[4][2];
#pragma unroll
        for (int r = 0; r < 4; r++) { acc[r][0] = bv0; acc[r][1] = bv1; }
        const float* wp = Wd + o2;
#pragma unroll 4
        for (int k = 0; k < HH; k++) {
            float2 w2 = *(const float2*)wp; wp += OUTSZ;
#pragma unroll
            for (int r = 0; r < 4; r++) {
                float hv = sp[(r << 10) + k];
                acc[r][0] = fmaf(hv, w2.x, acc[r][0]);
                acc[r][1] = fmaf(hv, w2.y, acc[r][1]);
            }
        }
#pragma unroll
        for (int r = 0; r < 4; r++) {
            float2 o = make_float2(acc[r][0], acc[r][1]);
            *(float2*)(out + (size_t)(t0 + r) * OUTSZ + o2) = o;
        }
    }
}

// ---------------------------------------------------------------------------
// Launcher: exactly ONE kernel launch (graph-capturable, allocation-free).
// ---------------------------------------------------------------------------
extern "C" void kernel_launch(void* const* d_in, const int* in_sizes, int n_in,
                              void* d_out, int out_size)
{
    (void)in_sizes; (void)n_in; (void)out_size;
    const float* X     = (const float*)d_in[0];
    const float* state = (const float*)d_in[1];
    const float* W0    = (const float*)d_in[2];
    const float* b0    = (const float*)d_in[3];
    const float* W1    = (const float*)d_in[4];
    const float* b1    = (const float*)d_in[5];
    const float* Wd    = (const float*)d_in[6];
    const float* bd    = (const float*)d_in[7];

    lstm_persistent<<<NBLK, NTHR>>>(X, state, W0, b0, W1, b1, Wd, bd,
                                    (float*)d_out);
}

// round 6
// speedup vs baseline: 1.3129x; 1.3129x over previous
#include <cuda_runtime.h>
#include <math.h>

// Problem constants
#define TT    512
#define INSZ  512
#define HH    1024
#define OUTSZ 512
#define NG    4096
#define BSEL  63            // only batch row 63 affects the output
#define K0    1536          // INSZ + HH
#define K1    2048          // HH + HH
#define NBLK  128
#define NTHR  256
#define NBAR  514u          // 1 init barrier + 513 phase barriers per run

// ---------------------------------------------------------------------------
// Static device scratch.
// ---------------------------------------------------------------------------
__device__ float    g_W1p[(size_t)NBLK * K1 * 32];   // packed layer-1 weights (33.6 MB)
__device__ float    g_h0[2][HH];                     // h0 ping-pong
__device__ float    g_h1init[HH];                    // initial h1
__device__ float    g_hist[TT][HH];                  // h1(t) history
__device__ unsigned g_flags[NBLK * 32];              // one 128B line per block
__device__ unsigned g_base = 0u;                     // persistent phase base (replay-safe)

__device__ __forceinline__ float sigf(float x) { return 1.0f / (1.0f + expf(-x)); }

// Distributed grid barrier: per-block flag lines, no atomics, no shared hotspot.
__device__ __forceinline__ void gridbar(unsigned target) {
    __threadfence();                 // release this thread's prior global writes
    __syncthreads();                 // all threads' fences done
    if (threadIdx.x == 0)
        *(volatile unsigned*)&g_flags[blockIdx.x << 5] = target;
    if (threadIdx.x < NBLK) {
        volatile unsigned* f = &g_flags[threadIdx.x << 5];
        while (*f < target) { }      // each thread polls a DISTINCT line
        __threadfence();             // acquire
    }
    __syncthreads();
}

__device__ __forceinline__ void facc(float4& a, float f, float4 w) {
    a.x = fmaf(f, w.x, a.x); a.y = fmaf(f, w.y, a.y);
    a.z = fmaf(f, w.z, a.z); a.w = fmaf(f, w.w, a.w);
}

// SMEM layout (floats): W0 pack | staged inputs | reductions | small state
#define S_W0   0                    // 49152  (K0 x 32)
#define S_IN   49152                // 2560   [x 512 | h0prev 1024 | h1pp 1024]
#define S_RED0 51712                // 512    (16 x 32)
#define S_RED1 52224                // 512
#define S_ZF0  52736                // 32
#define S_ZF1  52768                // 32
#define S_C0   52800                // 8
#define S_C1   52808                // 8
#define S_B0   52816                // 32
#define S_B1   52848                // 32
#define S_TOT  52880                // floats -> 211,520 B dynamic smem

__global__ __launch_bounds__(NTHR) void lstm_persistent(
    const float* __restrict__ X,
    const float* __restrict__ state,
    const float* __restrict__ W0, const float* __restrict__ b0,
    const float* __restrict__ W1, const float* __restrict__ b1,
    const float* __restrict__ Wd, const float* __restrict__ bd,
    float* __restrict__ out)
{
    extern __shared__ __align__(16) float sm[];
    float* w0s   = sm + S_W0;
    float* in_sh = sm + S_IN;
    float* red0  = sm + S_RED0;
    float* red1  = sm + S_RED1;
    float* zf0   = sm + S_ZF0;
    float* zf1   = sm + S_ZF1;
    float* c0s   = sm + S_C0;
    float* c1s   = sm + S_C1;
    float* b0s   = sm + S_B0;
    float* b1s   = sm + S_B1;

    const int tid   = threadIdx.x;
    const int bid   = blockIdx.x;
    const int hbase = bid << 3;

    const unsigned base = *(volatile unsigned*)&g_base;

    // ---- one-time: pack this block's 32 gate-columns ----
    // layer 0 -> SMEM (stays resident), layer 1 -> block-private global slice
    for (int e = tid; e < K0 * 32; e += NTHR) {
        int k = e >> 5, lane = e & 31;
        int col = (lane >> 3) * HH + hbase + (lane & 7);
        w0s[e] = __ldg(W0 + (size_t)k * NG + col);
    }
    float* W1pb = g_W1p + (size_t)bid * (K1 * 32);
    for (int e = tid; e < K1 * 32; e += NTHR) {
        int k = e >> 5, lane = e & 31;
        int col = (lane >> 3) * HH + hbase + (lane & 7);
        W1pb[e] = __ldg(W1 + (size_t)k * NG + col);
    }

    // ---- init state (row 63): [c0 | h0 | c1 | h1]; each block owns 8 cols ----
    const float* srow = state + (size_t)BSEL * 4 * HH;
    if (tid < 8) {
        c0s[tid] = srow[hbase + tid];
        c1s[tid] = srow[2 * HH + hbase + tid];
        __stcg(&g_h0[1][hbase + tid],   srow[HH + hbase + tid]);     // read at p=0
        __stcg(&g_h1init[hbase + tid],  srow[3 * HH + hbase + tid]);
    }
    if (tid < 32) {
        int col = (tid >> 3) * HH + hbase + (tid & 7);
        b0s[tid] = b0[col];
        b1s[tid] = b1[col];
    }
    gridbar(base + 1u);

    // ---- pipelined time loop: phase p does layer0(t=p) and layer1(t=p-1) ----
    const float* Xrow = X + (size_t)BSEL * TT * INSZ;
    for (int p = 0; p <= TT; p++) {
        const int rbuf = (p + 1) & 1;      // h0(p-1) lives here
        const int wbuf = p & 1;            // h0(p) written here

        // stage inputs: x[p] | h0(p-1) | h1(p-2)
        if (p < TT && tid < 128)
            ((float4*)in_sh)[tid] = __ldg((const float4*)(Xrow + (size_t)p * INSZ) + tid);
        ((float4*)in_sh)[128 + tid] = __ldcg((const float4*)g_h0[rbuf] + tid);
        if (p >= 1) {
            const float* h1src = (p == 1) ? g_h1init : g_hist[p - 2];
            ((float4*)in_sh)[384 + tid] = __ldcg((const float4*)h1src + tid);
        }
        __syncthreads();

        if (tid < 128) {
            // ---- layer 0 GEMV from SMEM weights (skip at p == TT) ----
            if (p < TT) {
                const int cg = tid & 7, s = tid >> 3;     // 16 slices x 8 col-groups
                float4 acc = make_float4(0.f, 0.f, 0.f, 0.f);
                const float* wp = w0s + (s * 96) * 32 + (cg << 2);
                const float* ip = in_sh + s * 96;
#pragma unroll 6
                for (int g4 = 0; g4 < 24; g4++) {
                    float4 f4 = *(const float4*)(ip + (g4 << 2));
                    float4 wa = *(const float4*)(wp);
                    float4 wb = *(const float4*)(wp + 32);
                    float4 wc = *(const float4*)(wp + 64);
                    float4 wd4 = *(const float4*)(wp + 96);
                    wp += 128;
                    facc(acc, f4.x, wa); facc(acc, f4.y, wb);
                    facc(acc, f4.z, wc); facc(acc, f4.w, wd4);
                }
                ((float4*)red0)[(s << 3) + cg] = acc;
            }
        } else {
            // ---- layer 1 GEMV from packed L2 weights (skip at p == 0) ----
            if (p >= 1) {
                const int t1 = tid - 128;
                const int cg = t1 & 7, s = t1 >> 3;       // 16 slices x 8 col-groups
                float4 acc = make_float4(0.f, 0.f, 0.f, 0.f);
                const float* wp = W1pb + (size_t)(s << 7) * 32 + (cg << 2);
                const float* ip = in_sh + 512 + (s << 7);
#pragma unroll 4
                for (int g4 = 0; g4 < 32; g4++) {
                    float4 f4 = *(const float4*)(ip + (g4 << 2));
                    float4 wa = __ldcg((const float4*)(wp));
                    float4 wb = __ldcg((const float4*)(wp + 32));
                    float4 wc = __ldcg((const float4*)(wp + 64));
                    float4 wd4 = __ldcg((const float4*)(wp + 96));
                    wp += 128;
                    facc(acc, f4.x, wa); facc(acc, f4.y, wb);
                    facc(acc, f4.z, wc); facc(acc, f4.w, wd4);
                }
                ((float4*)red1)[(s << 3) + cg] = acc;
            }
        }
        __syncthreads();

        // ---- reductions ----
        if (tid < 32 && p < TT) {
            float sum = 0.f;
#pragma unroll
            for (int ss = 0; ss < 16; ss++) sum += red0[(ss << 5) + tid];
            zf0[tid] = sum + b0s[tid];
        }
        if (tid >= 128 && tid < 160 && p >= 1) {
            const int t1 = tid - 128;
            float sum = 0.f;
#pragma unroll
            for (int ss = 0; ss < 16; ss++) sum += red1[(ss << 5) + t1];
            zf1[t1] = sum + b1s[t1];
        }
        __syncthreads();

        // ---- cell epilogues ----
        if (tid < 8 && p < TT) {
            int j = tid;
            float zi = zf0[j], zj = zf0[8 + j], zff = zf0[16 + j], zo = zf0[24 + j];
            float cn = sigf(zff + 1.0f) * c0s[j] + sigf(zi) * tanhf(zj);
            c0s[j] = cn;
            __stcg(&g_h0[wbuf][hbase + j], sigf(zo) * tanhf(cn));
        }
        if (tid >= 128 && tid < 136 && p >= 1) {
            int j = tid - 128;
            float zi = zf1[j], zj = zf1[8 + j], zff = zf1[16 + j], zo = zf1[24 + j];
            float cn = sigf(zff + 1.0f) * c1s[j] + sigf(zi) * tanhf(zj);
            c1s[j] = cn;
            __stcg(&g_hist[p - 1][hbase + j], sigf(zo) * tanhf(cn));
        }

        gridbar(base + 2u + (unsigned)p);
    }

    // ---- dense: out[t][o] = hist[t] @ Wd + bd; block owns 4 t-rows ----
    {
        float* hst = sm;                 // reuse w0s region (4096 floats)
        int t0 = bid << 2;
#pragma unroll
        for (int r = 0; r < 4; r++)
            ((float4*)hst)[(r << 8) + tid] =
                __ldcg((const float4*)g_hist[t0 + r] + tid);
        __syncthreads();

        int o2 = tid << 1;
        float bv0 = bd[o2], bv1 = bd[o2 + 1];
        float acc[4][2];
#pragma unroll
        for (int r = 0; r < 4; r++) { acc[r][0] = bv0; acc[r][1] = bv1; }
        const float* wp = Wd + o2;
#pragma unroll 4
        for (int k = 0; k < HH; k++) {
            float2 w2 = *(const float2*)wp; wp += OUTSZ;
#pragma unroll
            for (int r = 0; r < 4; r++) {
                float hv = hst[(r << 10) + k];
                acc[r][0] = fmaf(hv, w2.x, acc[r][0]);
                acc[r][1] = fmaf(hv, w2.y, acc[r][1]);
            }
        }
#pragma unroll
        for (int r = 0; r < 4; r++)
            *(float2*)(out + (size_t)(t0 + r) * OUTSZ + o2) =
                make_float2(acc[r][0], acc[r][1]);
    }

    // advance the persistent phase base for the next graph replay
    if (bid == 0 && tid == 0)
        *(volatile unsigned*)&g_base = base + NBAR;
}

// ---------------------------------------------------------------------------
// Launcher: ONE kernel launch, >48KB dynamic smem opted in.
// ---------------------------------------------------------------------------
extern "C" void kernel_launch(void* const* d_in, const int* in_sizes, int n_in,
                              void* d_out, int out_size)
{
    (void)in_sizes; (void)n_in; (void)out_size;
    const float* X     = (const float*)d_in[0];
    const float* state = (const float*)d_in[1];
    const float* W0    = (const float*)d_in[2];
    const float* b0    = (const float*)d_in[3];
    const float* W1    = (const float*)d_in[4];
    const float* b1    = (const float*)d_in[5];
    const float* Wd    = (const float*)d_in[6];
    const float* bd    = (const float*)d_in[7];

    static int configured = 0;
    if (!configured) {
        cudaFuncSetAttribute(lstm_persistent,
                             cudaFuncAttributeMaxDynamicSharedMemorySize,
                             S_TOT * sizeof(float));
        configured = 1;
    }

    lstm_persistent<<<NBLK, NTHR, S_TOT * sizeof(float)>>>(
        X, state, W0, b0, W1, b1, Wd, bd, (float*)d_out);
}

// round 7
// speedup vs baseline: 3.2398x; 2.4676x over previous
#include <cuda_runtime.h>
#include <math.h>

// Problem constants
#define TT    512
#define INSZ  512
#define HH    1024
#define OUTSZ 512
#define NG    4096
#define BSEL  63            // only batch row 63 affects the output
#define K0    1536          // INSZ + HH
#define K1    2048          // HH + HH
#define NBLK  128
#define NTHR  512
#define NBAR  514u          // 1 init barrier + 513 phase barriers per run

// ---------------------------------------------------------------------------
// Static device scratch.
// ---------------------------------------------------------------------------
__device__ float    g_W1p[(size_t)NBLK * K1 * 32];   // packed layer-1 weights (33.6 MB)
__device__ float    g_h0[2][HH];                     // h0 ping-pong
__device__ float    g_h1init[HH];                    // initial h1
__device__ float    g_hist[TT][HH];                  // h1(t) history
__device__ unsigned g_flags[NBLK * 32];              // one 128B line per block
__device__ unsigned g_base = 0u;                     // persistent phase base (replay-safe)

__device__ __forceinline__ float sigf(float x) { return 1.0f / (1.0f + expf(-x)); }

// Distributed grid barrier: per-block flag lines, scoped release/acquire
// (NO __threadfence -> no heavyweight MEMBAR / L1D flush on the hot path).
// bar.sync before the release store gives cumulativity: the releasing
// thread publishes ALL block threads' prior global writes.
__device__ __forceinline__ void gridbar(unsigned target) {
    __syncthreads();
    if (threadIdx.x == 0) {
        unsigned* f = &g_flags[blockIdx.x << 5];
        asm volatile("st.release.gpu.u32 [%0], %1;" :: "l"(f), "r"(target) : "memory");
    }
    if (threadIdx.x < NBLK) {
        unsigned* f = &g_flags[threadIdx.x << 5];
        unsigned v;
        do {
            asm volatile("ld.acquire.gpu.u32 %0, [%1];" : "=r"(v) : "l"(f) : "memory");
        } while (v < target);
    }
    __syncthreads();
}

__device__ __forceinline__ void facc(float4& a, float f, float4 w) {
    a.x = fmaf(f, w.x, a.x); a.y = fmaf(f, w.y, a.y);
    a.z = fmaf(f, w.z, a.z); a.w = fmaf(f, w.w, a.w);
}

// SMEM layout (floats)
#define S_W0   0                    // 49152  (K0 x 32) layer-0 packed weights
#define S_IN   49152                // 2560   [x 512 | h0prev 1024 | h1pp 1024]
#define S_RED0 51712                // 1024   (32 x 32)
#define S_RED1 52736                // 1024
#define S_ZF0  53760                // 32
#define S_ZF1  53792                // 32
#define S_C0   53824                // 8
#define S_C1   53832                // 8
#define S_B0   53840                // 32
#define S_B1   53872                // 32
#define S_TOT  53904                // floats -> 215,616 B dynamic smem

__global__ __launch_bounds__(NTHR, 1) void lstm_persistent(
    const float* __restrict__ X,
    const float* __restrict__ state,
    const float* __restrict__ W0, const float* __restrict__ b0,
    const float* __restrict__ W1, const float* __restrict__ b1,
    const float* __restrict__ Wd, const float* __restrict__ bd,
    float* __restrict__ out)
{
    extern __shared__ __align__(16) float sm[];
    float* w0s   = sm + S_W0;
    float* in_sh = sm + S_IN;
    float* red0  = sm + S_RED0;
    float* red1  = sm + S_RED1;
    float* zf0   = sm + S_ZF0;
    float* zf1   = sm + S_ZF1;
    float* c0s   = sm + S_C0;
    float* c1s   = sm + S_C1;
    float* b0s   = sm + S_B0;
    float* b1s   = sm + S_B1;

    const int tid   = threadIdx.x;
    const int bid   = blockIdx.x;
    const int hbase = bid << 3;

    const unsigned base = *(volatile unsigned*)&g_base;

    // ---- one-time: pack this block's 32 gate-columns ----
    for (int e = tid; e < K0 * 32; e += NTHR) {
        int k = e >> 5, lane = e & 31;
        int col = (lane >> 3) * HH + hbase + (lane & 7);
        w0s[e] = __ldg(W0 + (size_t)k * NG + col);
    }
    float* W1pb = g_W1p + (size_t)bid * (K1 * 32);
    for (int e = tid; e < K1 * 32; e += NTHR) {
        int k = e >> 5, lane = e & 31;
        int col = (lane >> 3) * HH + hbase + (lane & 7);
        W1pb[e] = __ldg(W1 + (size_t)k * NG + col);
    }

    // ---- init state (row 63): [c0 | h0 | c1 | h1] ----
    const float* srow = state + (size_t)BSEL * 4 * HH;
    if (tid < 8) {
        c0s[tid] = srow[hbase + tid];
        c1s[tid] = srow[2 * HH + hbase + tid];
        __stcg(&g_h0[1][hbase + tid],  srow[HH + hbase + tid]);      // read at p=0
        __stcg(&g_h1init[hbase + tid], srow[3 * HH + hbase + tid]);
    }
    if (tid < 32) {
        int col = (tid >> 3) * HH + hbase + (tid & 7);
        b0s[tid] = b0[col];
        b1s[tid] = b1[col];
    }
    gridbar(base + 1u);

    // ---- pipelined time loop: phase p does layer0(t=p) and layer1(t=p-1) ----
    const float* Xrow = X + (size_t)BSEL * TT * INSZ;
    for (int p = 0; p <= TT; p++) {
        const int rbuf = (p + 1) & 1;      // h0(p-1) lives here
        const int wbuf = p & 1;            // h0(p) written here

        // stage inputs: f4 slots [0:128) = x(p), [128:384) = h0(p-1),
        //               [384:640) = h1(p-2)
        const float* h1src = (p == 1) ? g_h1init : g_hist[(p >= 2) ? (p - 2) : 0];
        for (int e = tid; e < 640; e += NTHR) {
            float4 v = make_float4(0.f, 0.f, 0.f, 0.f);
            if (e < 128) {
                if (p < TT) v = __ldg((const float4*)(Xrow + (size_t)p * INSZ) + e);
            } else if (e < 384) {
                v = __ldcg((const float4*)g_h0[rbuf] + (e - 128));
            } else {
                if (p >= 1) v = __ldcg((const float4*)h1src + (e - 384));
            }
            ((float4*)in_sh)[e] = v;
        }
        __syncthreads();

        if (tid < 256) {
            // ---- layer 0 GEMV from SMEM weights (warps 0-7) ----
            if (p < TT) {
                const int cg = tid & 7, s = tid >> 3;     // 32 slices x 8 col-groups
                float4 acc = make_float4(0.f, 0.f, 0.f, 0.f);
                const float* wp = w0s + (s * 48) * 32 + (cg << 2);
                const float* ip = in_sh + s * 48;
#pragma unroll
                for (int g4 = 0; g4 < 12; g4++) {
                    float4 f4 = *(const float4*)(ip + (g4 << 2));
                    float4 wa  = *(const float4*)(wp);
                    float4 wb  = *(const float4*)(wp + 32);
                    float4 wc  = *(const float4*)(wp + 64);
                    float4 wd4 = *(const float4*)(wp + 96);
                    wp += 128;
                    facc(acc, f4.x, wa); facc(acc, f4.y, wb);
                    facc(acc, f4.z, wc); facc(acc, f4.w, wd4);
                }
                ((float4*)red0)[(s << 3) + cg] = acc;
            }
        } else {
            // ---- layer 1 GEMV from packed L2 weights (warps 8-15),
            //      double-buffered 8xfloat4 register pipeline ----
            if (p >= 1) {
                const int t1 = tid - 256;
                const int cg = t1 & 7, s = t1 >> 3;       // 32 slices x 8 col-groups
                const float* wp = W1pb + (size_t)(s << 6) * 32 + (cg << 2);
                const float* ip = in_sh + 512 + (s << 6);
                float4 acc = make_float4(0.f, 0.f, 0.f, 0.f);
                float4 bufA[8], bufB[8];
#pragma unroll
                for (int i = 0; i < 8; i++) bufA[i] = __ldcg((const float4*)(wp + (i << 5)));
                wp += 256;
#pragma unroll
                for (int b = 0; b < 8; b++) {
                    float4* cur = (b & 1) ? bufB : bufA;
                    float4* nxt = (b & 1) ? bufA : bufB;
                    if (b < 7) {
#pragma unroll
                        for (int i = 0; i < 8; i++)
                            nxt[i] = __ldcg((const float4*)(wp + (i << 5)));
                        wp += 256;
                    }
                    float4 fa = *(const float4*)(ip + (b << 3));
                    float4 fb = *(const float4*)(ip + (b << 3) + 4);
                    facc(acc, fa.x, cur[0]); facc(acc, fa.y, cur[1]);
                    facc(acc, fa.z, cur[2]); facc(acc, fa.w, cur[3]);
                    facc(acc, fb.x, cur[4]); facc(acc, fb.y, cur[5]);
                    facc(acc, fb.z, cur[6]); facc(acc, fb.w, cur[7]);
                }
                ((float4*)red1)[(s << 3) + cg] = acc;
            }
        }
        __syncthreads();

        // ---- reductions (32 slices each) ----
        if (tid < 32 && p < TT) {
            float sum = 0.f;
#pragma unroll
            for (int ss = 0; ss < 32; ss++) sum += red0[(ss << 5) + tid];
            zf0[tid] = sum + b0s[tid];
        }
        if (tid >= 256 && tid < 288 && p >= 1) {
            const int t1 = tid - 256;
            float sum = 0.f;
#pragma unroll
            for (int ss = 0; ss < 32; ss++) sum += red1[(ss << 5) + t1];
            zf1[t1] = sum + b1s[t1];
        }
        __syncthreads();

        // ---- cell epilogues ----
        if (tid < 8 && p < TT) {
            int j = tid;
            float zi = zf0[j], zj = zf0[8 + j], zff = zf0[16 + j], zo = zf0[24 + j];
            float cn = sigf(zff + 1.0f) * c0s[j] + sigf(zi) * tanhf(zj);
            c0s[j] = cn;
            __stcg(&g_h0[wbuf][hbase + j], sigf(zo) * tanhf(cn));
        }
        if (tid >= 256 && tid < 264 && p >= 1) {
            int j = tid - 256;
            float zi = zf1[j], zj = zf1[8 + j], zff = zf1[16 + j], zo = zf1[24 + j];
            float cn = sigf(zff + 1.0f) * c1s[j] + sigf(zi) * tanhf(zj);
            c1s[j] = cn;
            __stcg(&g_hist[p - 1][hbase + j], sigf(zo) * tanhf(cn));
        }

        gridbar(base + 2u + (unsigned)p);
    }

    // ---- dense: out[t][o] = hist[t] @ Wd + bd; block owns 4 t-rows ----
    {
        float* hst = sm;                 // reuse w0s region (4096 floats)
        int t0 = bid << 2;
        for (int e = tid; e < 1024; e += NTHR)
            ((float4*)hst)[e] = __ldcg((const float4*)g_hist[t0 + (e >> 8)] + (e & 255));
        __syncthreads();

        int r  = tid >> 7;               // 0..3  (t-row within block)
        int o0 = (tid & 127) << 2;       // 0..508
        float4 acc = make_float4(bd[o0], bd[o0 + 1], bd[o0 + 2], bd[o0 + 3]);
        const float* hrow = hst + (r << 10);
        const float* wp = Wd + o0;
#pragma unroll 8
        for (int k = 0; k < HH; k++) {
            float4 w4 = __ldcg((const float4*)wp);
            wp += OUTSZ;
            facc(acc, hrow[k], w4);
        }
        *(float4*)(out + (size_t)(t0 + r) * OUTSZ + o0) = acc;
    }

    // advance the persistent phase base for the next graph replay
    if (bid == 0 && tid == 0)
        *(volatile unsigned*)&g_base = base + NBAR;
}

// ---------------------------------------------------------------------------
// Launcher: ONE kernel launch, >48KB dynamic smem opted in.
// ---------------------------------------------------------------------------
extern "C" void kernel_launch(void* const* d_in, const int* in_sizes, int n_in,
                              void* d_out, int out_size)
{
    (void)in_sizes; (void)n_in; (void)out_size;
    const float* X     = (const float*)d_in[0];
    const float* state = (const float*)d_in[1];
    const float* W0    = (const float*)d_in[2];
    const float* b0    = (const float*)d_in[3];
    const float* W1    = (const float*)d_in[4];
    const float* b1    = (const float*)d_in[5];
    const float* Wd    = (const float*)d_in[6];
    const float* bd    = (const float*)d_in[7];

    static int configured = 0;
    if (!configured) {
        cudaFuncSetAttribute(lstm_persistent,
                             cudaFuncAttributeMaxDynamicSharedMemorySize,
                             S_TOT * sizeof(float));
        configured = 1;
    }

    lstm_persistent<<<NBLK, NTHR, S_TOT * sizeof(float)>>>(
        X, state, W0, b0, W1, b1, Wd, bd, (float*)d_out);
}